// round 6
// baseline (speedup 1.0000x reference)
#include <cuda_runtime.h>
#include <cstdint>

// ---------------------------------------------------------------------------
// Seq2seq BiLSTM (encoder 336 steps + autoregressive decoder 24 iters)
// Persistent cooperative kernel, fp32 FFMA, custom flag-array grid barrier.
//
// Mapping: grid = 128 CTAs = 2 dirs x 4 batch-tiles(32) x 16 j-tiles(16).
// Each CTA owns a fixed (dir, b-slice, j-slice) for the WHOLE run:
//   - weights slice (64 gate-rows x K=320) staged in SMEM once per phase
//   - cell state c lives in registers (4 per thread) for the whole run
//   - h published to a global buffer each round; grid barrier between rounds
// ---------------------------------------------------------------------------

#define NBLK 128
#define NTHR 128

namespace {
constexpr int BATCH = 128;
constexpr int SEQLEN = 336;
constexpr int PRED = 24;
constexpr int IN = 64;
constexpr int HID = 256;
constexpr int KTOT = IN + HID;          // 320
constexpr int WS = 68;                  // k-major W smem row stride (floats), 68%32=4
constexpr int AS = 328;                 // A smem row stride (floats), 16B-aligned rows
constexpr int SMEM_FLOATS = KTOT * WS + 32 * AS + 64;  // W + A + bias = 32320 floats
constexpr int SMEM_BYTES = SMEM_FLOATS * 4;            // 129280 B
}

// Persistent device state
__device__ float g_h[2 * BATCH * HID];          // hidden states, both dirs
__device__ float g_y[PRED * BATCH * IN];        // decoder outputs (autoregressive feed)
__device__ int   g_flags[NBLK];                 // grid barrier flags

__device__ __forceinline__ float sigmoidf_(float x) {
    return 1.0f / (1.0f + __expf(-x));
}

// Flat grid barrier: each CTA publishes its round number; every thread polls
// one CTA's flag. No contended atomics. Requires blockDim.x == gridDim.x == 128.
__device__ __forceinline__ void gridbar(int round) {
    __threadfence();                       // make this thread's h-stores visible
    __syncthreads();                       // all threads of CTA fenced
    if (threadIdx.x == 0)
        ((volatile int*)g_flags)[blockIdx.x] = round;   // release-publish
    volatile int* f = (volatile int*)g_flags;
    if (f[threadIdx.x] < round) {
        while (f[threadIdx.x] < round) { __nanosleep(32); }
    }
    __syncthreads();
    __threadfence();                       // acquire before reading peers' h
}

// Stage per-phase weight slice into SMEM, k-major:
//   Wsm[k*WS + c],  c = gate*16 + jj,  row = gate*256 + j0 + jj
//   k<64 -> Wih row, else Whh row.  bsum[c] = bih+bhh.
__device__ void load_phase_weights(float* Wsm, float* bsum,
                                   const float* __restrict__ Wih,
                                   const float* __restrict__ Whh,
                                   const float* __restrict__ bih,
                                   const float* __restrict__ bhh,
                                   int d, int j0) {
    for (int idx = threadIdx.x; idx < 64 * KTOT; idx += NTHR) {
        int c = idx / KTOT;
        int k = idx - c * KTOT;
        int g = c >> 4, jj = c & 15;
        int row = g * 256 + j0 + jj;
        float v = (k < IN) ? Wih[(d * 1024 + row) * IN + k]
                           : Whh[(d * 1024 + row) * HID + (k - IN)];
        Wsm[k * WS + c] = v;
    }
    for (int c = threadIdx.x; c < 64; c += NTHR) {
        int g = c >> 4, jj = c & 15;
        int row = g * 256 + j0 + jj;
        bsum[c] = bih[d * 1024 + row] + bhh[d * 1024 + row];
    }
}

// One LSTM cell step for this CTA's slice.
// src: base pointer of the input vectors for this timestep (row b at
//      src + b*rowStride, 64 floats). h read from g_h (L2, __ldcg).
__device__ void cell_round(const float* __restrict__ src, int rowStride,
                           int d, int b0, int j0,
                           const float* Wsm, float* Asm, const float* bsum,
                           float c_reg[4]) {
    const int tid = threadIdx.x;

    // ---- stage A = [x_t | h] tile: 32 rows x 320 floats (80 float4/row)
    for (int it = 0; it < (32 * 80) / NTHR; it++) {
        int idx = tid + it * NTHR;
        int row = idx / 80;
        int slot = idx - row * 80;
        int b = b0 + row;
        float4 v;
        if (slot < 16)
            v = __ldcg((const float4*)(src + (size_t)b * rowStride) + slot);
        else
            v = __ldcg((const float4*)(g_h + ((d << 7) + b) * HID) + (slot - 16));
        *(float4*)(Asm + row * AS + slot * 4) = v;
    }
    __syncthreads();

    // ---- GEMM: thread computes 4 batch rows x 4 gates of one hidden unit j
    const int tj = tid & 15;       // hidden unit within j-tile
    const int tb = tid >> 4;       // batch group 0..7 (4 rows each)
    float acc[4][4];
#pragma unroll
    for (int g = 0; g < 4; g++) {
        float bv = bsum[g * 16 + tj];
#pragma unroll
        for (int bi = 0; bi < 4; bi++) acc[bi][g] = bv;
    }

    const float* A0 = Asm + (tb * 4 + 0) * AS;
    const float* A1 = A0 + AS;
    const float* A2 = A1 + AS;
    const float* A3 = A2 + AS;

#pragma unroll 2
    for (int k = 0; k < KTOT; k += 4) {
        float4 a0 = *(const float4*)(A0 + k);
        float4 a1 = *(const float4*)(A1 + k);
        float4 a2 = *(const float4*)(A2 + k);
        float4 a3 = *(const float4*)(A3 + k);
        float av[4][4] = {{a0.x, a0.y, a0.z, a0.w},
                          {a1.x, a1.y, a1.z, a1.w},
                          {a2.x, a2.y, a2.z, a2.w},
                          {a3.x, a3.y, a3.z, a3.w}};
#pragma unroll
        for (int kk = 0; kk < 4; kk++) {
            const float* wr = Wsm + (k + kk) * WS + tj;
            float w0 = wr[0];
            float w1 = wr[16];
            float w2 = wr[32];
            float w3 = wr[48];
#pragma unroll
            for (int bi = 0; bi < 4; bi++) {
                float a = av[bi][kk];
                acc[bi][0] = fmaf(a, w0, acc[bi][0]);
                acc[bi][1] = fmaf(a, w1, acc[bi][1]);
                acc[bi][2] = fmaf(a, w2, acc[bi][2]);
                acc[bi][3] = fmaf(a, w3, acc[bi][3]);
            }
        }
    }

    // ---- pointwise LSTM update (c stays in registers), publish h
    int j = j0 + tj;
#pragma unroll
    for (int bi = 0; bi < 4; bi++) {
        int b = b0 + tb * 4 + bi;
        float gi = acc[bi][0], gf = acc[bi][1], gg = acc[bi][2], go = acc[bi][3];
        float cn = sigmoidf_(gf) * c_reg[bi] + sigmoidf_(gi) * tanhf(gg);
        float hn = sigmoidf_(go) * tanhf(cn);
        c_reg[bi] = cn;
        g_h[((d << 7) + b) * HID + j] = hn;
    }
}

__global__ void __launch_bounds__(NTHR, 1)
lstm_s2s_kernel(const float* __restrict__ x,
                const float* __restrict__ eWih, const float* __restrict__ eWhh,
                const float* __restrict__ ebih, const float* __restrict__ ebhh,
                const float* __restrict__ dWih, const float* __restrict__ dWhh,
                const float* __restrict__ dbih, const float* __restrict__ dbhh,
                const float* __restrict__ linW, const float* __restrict__ linb,
                float* __restrict__ out) {
    extern __shared__ float smem[];
    float* Wsm = smem;                       // [320][68]
    float* Asm = Wsm + KTOT * WS;            // [32][328]
    float* bsum = Asm + 32 * AS;             // [64]

    const int ct = blockIdx.x;
    const int d = ct >> 6;
    const int rem = ct & 63;
    const int b0 = (rem >> 4) * 32;
    const int j0 = (rem & 15) * 16;
    const int tid = threadIdx.x;

    int round = 0;
    float c_reg[4] = {0.f, 0.f, 0.f, 0.f};

    // zero this CTA's h slice (fresh state every launch/replay)
    for (int idx = tid; idx < 32 * 16; idx += NTHR) {
        int bb = idx >> 4, jj = idx & 15;
        g_h[((d << 7) + b0 + bb) * HID + j0 + jj] = 0.f;
    }

    load_phase_weights(Wsm, bsum, eWih, eWhh, ebih, ebhh, d, j0);
    gridbar(++round);

    // ===== encoder: 336 rounds, fwd & bwd in parallel across CTA dirs =====
    for (int r = 0; r < SEQLEN; r++) {
        int t = (d == 0) ? r : (SEQLEN - 1 - r);
        cell_round(x + t * IN, SEQLEN * IN, d, b0, j0, Wsm, Asm, bsum, c_reg);
        gridbar(++round);
    }

    // switch to decoder weights (local SMEM swap; next cell_round's
    // __syncthreads orders these writes before first use)
    load_phase_weights(Wsm, bsum, dWih, dWhh, dbih, dbhh, d, j0);

    // ===== decoder: 24 autoregressive iterations =====
    for (int t = 0; t < PRED; t++) {
        int L = (t == 0) ? 1 : t;
        for (int s = 0; s < L; s++) {
            const float* src;
            int stride;
            if (t == 0) {
                src = x + (SEQLEN - 1) * IN;   // x[:, -1, :]
                stride = SEQLEN * IN;
            } else {
                int yi = (d == 0) ? s : (L - 1 - s);
                src = g_y + (size_t)yi * BATCH * IN;
                stride = IN;
            }
            cell_round(src, stride, d, b0, j0, Wsm, Asm, bsum, c_reg);
            gridbar(++round);
        }

        // ---- projection: y_t = concat(hF, hB) @ linW^T + linb  (CTAs 0..63)
        if (ct < 64) {
            int b = (ct << 1) + (tid >> 6);     // 2 batch rows per CTA
            int col = tid & 63;
            const float4* w4 = (const float4*)(linW + col * (2 * HID));
            const float4* h0 = (const float4*)(g_h + b * HID);
            const float4* h1 = (const float4*)(g_h + (BATCH + b) * HID);
            float s = linb[col];
#pragma unroll 4
            for (int q = 0; q < HID / 4; q++) {
                float4 f = __ldcg(h0 + q);
                float4 w = __ldg(w4 + q);
                s += f.x * w.x + f.y * w.y + f.z * w.z + f.w * w.w;
            }
#pragma unroll 4
            for (int q = 0; q < HID / 4; q++) {
                float4 f = __ldcg(h1 + q);
                float4 w = __ldg(w4 + HID / 4 + q);
                s += f.x * w.x + f.y * w.y + f.z * w.z + f.w * w.w;
            }
            g_y[((size_t)t * BATCH + b) * IN + col] = s;
            out[((size_t)b * PRED + t) * IN + col] = s;
        }
        gridbar(++round);
    }
}

extern "C" void kernel_launch(void* const* d_in, const int* in_sizes, int n_in,
                              void* d_out, int out_size) {
    const float* x    = (const float*)d_in[0];
    const float* eWih = (const float*)d_in[1];
    const float* eWhh = (const float*)d_in[2];
    const float* ebih = (const float*)d_in[3];
    const float* ebhh = (const float*)d_in[4];
    const float* dWih = (const float*)d_in[5];
    const float* dWhh = (const float*)d_in[6];
    const float* dbih = (const float*)d_in[7];
    const float* dbhh = (const float*)d_in[8];
    const float* linW = (const float*)d_in[9];
    const float* linb = (const float*)d_in[10];
    float* out = (float*)d_out;

    // reset barrier flags every launch (captured into the graph -> every replay)
    void* flagsPtr = nullptr;
    cudaGetSymbolAddress(&flagsPtr, g_flags);
    cudaMemsetAsync(flagsPtr, 0, sizeof(int) * NBLK, 0);

    cudaFuncSetAttribute(lstm_s2s_kernel,
                         cudaFuncAttributeMaxDynamicSharedMemorySize, SMEM_BYTES);

    lstm_s2s_kernel<<<NBLK, NTHR, SMEM_BYTES>>>(
        x, eWih, eWhh, ebih, ebhh, dWih, dWhh, dbih, dbhh, linW, linb, out);
}